// round 1
// baseline (speedup 1.0000x reference)
#include <cuda_runtime.h>

#define NB    11
#define NBINS 1331          // 11^3
#define ITER  20

__device__ int   g_hist[NBINS];
__device__ float g_cut01[3][NB];    // transformed cuts in [0,1]
__device__ float g_cut255[3][NB];   // transformed cuts * 255

// ---------------------------------------------------------------------------
// K1: zero histogram, sort+clip+pin the three 11-element cut arrays.
// Exactly mirrors: s = clip(sort(c),0,1); s[0]=0; s[-1]=1; (and *255 for compare)
// ---------------------------------------------------------------------------
__global__ void prep_kernel(const float* __restrict__ r_cut,
                            const float* __restrict__ g_cut,
                            const float* __restrict__ b_cut) {
    int t = threadIdx.x;
    for (int i = t; i < NBINS; i += blockDim.x) g_hist[i] = 0;
    if (t < 3) {
        const float* src = (t == 0) ? r_cut : (t == 1) ? g_cut : b_cut;
        float v[NB];
        for (int i = 0; i < NB; i++) v[i] = src[i];
        // insertion sort (ascending, stable)
        for (int i = 1; i < NB; i++) {
            float key = v[i];
            int j = i - 1;
            while (j >= 0 && v[j] > key) { v[j + 1] = v[j]; j--; }
            v[j + 1] = key;
        }
        for (int i = 0; i < NB; i++) v[i] = fminf(fmaxf(v[i], 0.0f), 1.0f);
        v[0] = 0.0f;
        v[NB - 1] = 1.0f;
        for (int i = 0; i < NB; i++) {
            g_cut01[t][i]  = v[i];
            g_cut255[t][i] = v[i] * 255.0f;
        }
    }
}

// ---------------------------------------------------------------------------
// K2: histogram. searchsorted(side=left) == count of (cut*255 < v).
// flat bin = ((ri-1)%11)*121 + ((gi-1)%11)*11 + ((bi-1)%11), with (i+10)%11.
// Cuts live in registers (fully unrolled constant indices). Per-block shared
// privatized histogram, flushed with global atomics.
// ---------------------------------------------------------------------------
__global__ void __launch_bounds__(256) hist_kernel(const float4* __restrict__ x, int n) {
    __shared__ int sh[NBINS];
    for (int i = threadIdx.x; i < NBINS; i += blockDim.x) sh[i] = 0;

    float rc[NB], gc[NB], bc[NB];
#pragma unroll
    for (int i = 0; i < NB; i++) {
        rc[i] = g_cut255[0][i];
        gc[i] = g_cut255[1][i];
        bc[i] = g_cut255[2][i];
    }
    __syncthreads();

    int stride = blockDim.x * gridDim.x;
    for (int idx = blockIdx.x * blockDim.x + threadIdx.x; idx < n; idx += stride) {
        float4 p = x[idx];
        int ri = 0, gi = 0, bi = 0;
#pragma unroll
        for (int j = 0; j < NB; j++) {
            ri += (rc[j] < p.x);
            gi += (gc[j] < p.y);
            bi += (bc[j] < p.z);
        }
        // (i + 10) % 11  with i in [0,11]
        ri += 10; if (ri >= 11) ri -= 11;
        gi += 10; if (gi >= 11) gi -= 11;
        bi += 10; if (bi >= 11) bi -= 11;
        atomicAdd(&sh[ri * 121 + gi * 11 + bi], 1);
    }
    __syncthreads();

    for (int i = threadIdx.x; i < NBINS; i += blockDim.x) {
        int v = sh[i];
        if (v) atomicAdd(&g_hist[i], v);
    }
}

// ---------------------------------------------------------------------------
// K3: top-20 stable selection (count desc, bin asc — matches stable
// argsort(-counts)) + final color computation.
// key = ((count << 11) | (1330 - bin)) + 1 ; removed entries set to 0.
// ---------------------------------------------------------------------------
__global__ void __launch_bounds__(512) topk_kernel(float* __restrict__ out) {
    __shared__ unsigned long long keys[NBINS];
    __shared__ unsigned long long warpmax[16];
    __shared__ int top[ITER];
    int t = threadIdx.x;

    for (int i = t; i < NBINS; i += blockDim.x) {
        unsigned long long c = (unsigned long long)(unsigned int)g_hist[i];
        keys[i] = ((c << 11) | (unsigned long long)(1330 - i)) + 1ull;
    }
    __syncthreads();

    for (int it = 0; it < ITER; it++) {
        unsigned long long m = 0;
        for (int i = t; i < NBINS; i += blockDim.x) {
            unsigned long long k = keys[i];
            m = (k > m) ? k : m;
        }
#pragma unroll
        for (int o = 16; o > 0; o >>= 1) {
            unsigned long long k = __shfl_xor_sync(0xffffffffu, m, o);
            m = (k > m) ? k : m;
        }
        if ((t & 31) == 0) warpmax[t >> 5] = m;
        __syncthreads();
        if (t < 32) {
            unsigned long long w = (t < 16) ? warpmax[t] : 0ull;
#pragma unroll
            for (int o = 16; o > 0; o >>= 1) {
                unsigned long long k = __shfl_xor_sync(0xffffffffu, w, o);
                w = (k > w) ? k : w;
            }
            if (t == 0) {
                int bin = 1330 - (int)((w - 1ull) & 0x7FFull);
                top[it] = bin;
                keys[bin] = 0ull;   // remove
            }
        }
        __syncthreads();
    }

    if (t < ITER) {
        int bin = top[t];
        int r = bin / 121;          // in [0,10]
        int g = (bin / 11) % 11;
        int b = bin % 11;
        r = min(r, NB - 2);
        g = min(g, NB - 2);
        b = min(b, NB - 2);
        float rv = 255.0f * (float)r / (float)NB + (g_cut01[0][r + 1] - g_cut01[0][r]) * 255.0f / 2.0f;
        float gv = 255.0f * (float)g / (float)NB + (g_cut01[1][g + 1] - g_cut01[1][g]) * 255.0f / 2.0f;
        float bv = 255.0f * (float)b / (float)NB + (g_cut01[2][b + 1] - g_cut01[2][b]) * 255.0f / 2.0f;
        out[t * 4 + 0] = rv;
        out[t * 4 + 1] = gv;
        out[t * 4 + 2] = bv;
        out[t * 4 + 3] = 255.0f;
    }
}

// ---------------------------------------------------------------------------
extern "C" void kernel_launch(void* const* d_in, const int* in_sizes, int n_in,
                              void* d_out, int out_size) {
    const float* x  = (const float*)d_in[0];
    const float* rc = (const float*)d_in[1];
    const float* gc = (const float*)d_in[2];
    const float* bc = (const float*)d_in[3];
    int n = in_sizes[0] / 4;   // number of pixels (float4 elements)

    prep_kernel<<<1, 256>>>(rc, gc, bc);
    hist_kernel<<<1184, 256>>>((const float4*)x, n);
    topk_kernel<<<1, 512>>>((float*)d_out);
}